// round 4
// baseline (speedup 1.0000x reference)
#include <cuda_runtime.h>

// Problem constants
#define B 256
#define T 512
#define H 512
#define O 2

// d_out layout (floats): out, hidden, net_units, read_out_units
#define HID_OFF (B * O)
#define NET_OFF (HID_OFF + B * H)
#define RO_OFF  (NET_OFF + B * T * H)

#define NCTA     128          // 16 j-tiles x 8 b-tiles; <= SM count -> all co-resident
#define NTHREADS 256
#define HROW     516          // Hs row stride in floats (pad: 4m+k bank spread)
// smem layout (floats): Ws[512][32] then Hs[32][HROW]
#define WS_FLOATS (512 * 32)
#define HS_FLOATS (32 * HROW)
#define SMEM_BYTES ((WS_FLOATS + HS_FLOATS) * 4)   // 131,584 B -> 1 CTA/SM

// Global-barrier counters, one per recurrence step (t = 1..511 -> idx 0..510)
__device__ int g_ctr[T];

// ---------------------------------------------------------------------------
// Pre-pass: net[b,t,j] = input[b,t,:].W_in[j,:] + b_in[j] + b_hh[j] + sigma*noise
// ---------------------------------------------------------------------------
__global__ __launch_bounds__(128) void pre_kernel(
    const float* __restrict__ input, const float* __restrict__ sigma,
    const float* __restrict__ noise, const float* __restrict__ W_in,
    const float* __restrict__ b_in,  const float* __restrict__ b_hh,
    float* __restrict__ net)
{
    const int t = blockIdx.x, b = blockIdx.y;
    const int j = threadIdx.x * 4;
    const size_t base = ((size_t)b * T + t) * H + j;
    const float in0 = input[((size_t)b * T + t) * 2 + 0];
    const float in1 = input[((size_t)b * T + t) * 2 + 1];
    const float sn  = sigma[0];
    float4 nz = *(const float4*)(noise + base);
    float4 r;
    float* rp = &r.x; const float* nzp = &nz.x;
    #pragma unroll
    for (int i = 0; i < 4; i++) {
        const int jj = j + i;
        rp[i] = in0 * W_in[jj * 2 + 0] + in1 * W_in[jj * 2 + 1]
              + b_in[jj] + b_hh[jj] + sn * nzp[i];
    }
    *(float4*)(net + base) = r;
}

// ---------------------------------------------------------------------------
// Persistent recurrence kernel. CTA bid: j-tile = bid & 15, b-tile = bid >> 4.
// W_hh tile resident in smem for the whole run; global spin barrier per step.
// ---------------------------------------------------------------------------
__global__ __launch_bounds__(NTHREADS, 1) void rnn_persistent_kernel(
    const float* __restrict__ W_hh,   // [H,H]
    float*       __restrict__ net)    // [B,T,H]
{
    extern __shared__ float smem[];
    float* Ws = smem;                 // Ws[k*32 + j]  (k = 0..511, j = 0..31)
    float* Hs = smem + WS_FLOATS;     // Hs[m*HROW + k]

    const int tid = threadIdx.x;
    const int j0  = (blockIdx.x & 15) * 32;
    const int b0  = (blockIdx.x >> 4) * 32;
    const int tm  = tid >> 3;         // 0..31 output row
    const int tn  = tid & 7;          // 0..7  -> 4 output cols

    // ---- Load W tile once: Ws[k][j] = W_hh[j0+j][k] ----
    {
        const int wj = tid & 31;          // 0..31 (W row within tile)
        const int wk = (tid >> 5) * 64;   // 8 groups x 64 k
        const float* src = W_hh + (size_t)(j0 + wj) * H + wk;
        #pragma unroll
        for (int c = 0; c < 64; c += 4) {
            float4 v = *(const float4*)(src + c);
            Ws[(wk + c + 0) * 32 + wj] = v.x;
            Ws[(wk + c + 1) * 32 + wj] = v.y;
            Ws[(wk + c + 2) * 32 + wj] = v.z;
            Ws[(wk + c + 3) * 32 + wj] = v.w;
        }
    }

    // ---- t = 0: h = relu(pre) (h0 = 0 -> no GEMM) ----
    {
        float* dst = net + ((size_t)(b0 + tm) * T + 0) * H + j0 + tn * 4;
        float4 p = __ldcg((const float4*)dst);
        p.x = fmaxf(p.x, 0.f); p.y = fmaxf(p.y, 0.f);
        p.z = fmaxf(p.z, 0.f); p.w = fmaxf(p.w, 0.f);
        *(float4*)dst = p;
    }

    // h-tile loader mapping: row = tid>>3, 8 threads cover 512 floats per row
    const int hr = tid >> 3;
    const int hc = (tid & 7) * 4;     // float4 col start, step 32 floats

    for (int t = 1; t < T; t++) {
        // ---- Global barrier: wait until every CTA finished writing step t-1 ----
        __syncthreads();
        if (tid == 0) {
            __threadfence();
            atomicAdd(&g_ctr[t - 1], 1);
            while (*(volatile int*)&g_ctr[t - 1] < NCTA) { }
            __threadfence();
        }
        __syncthreads();

        // ---- Load h_prev tile: Hs[r][k] = net[b0+r, t-1, k]  (bypass L1: cross-CTA data) ----
        {
            const float* src = net + ((size_t)(b0 + hr) * T + (size_t)(t - 1)) * H + hc;
            float* drow = Hs + hr * HROW + hc;
            #pragma unroll
            for (int i = 0; i < 16; i++) {
                float4 v = __ldcg((const float4*)(src + i * 32));
                *(float4*)(drow + i * 32) = v;
            }
        }
        __syncthreads();

        // ---- 512-k FFMA2 loop: 4 outputs (1 row x 4 cols) per thread ----
        unsigned long long a01 = 0ULL, a23 = 0ULL;   // packed f32x2 accumulators
        {
            const float* hrow = Hs + tm * HROW;
            const float* wcol = Ws + tn * 4;
            #pragma unroll 2
            for (int kb = 0; kb < 512; kb += 4) {
                float4 h4 = *(const float4*)(hrow + kb);
                #pragma unroll
                for (int u = 0; u < 4; u++) {
                    const float hv = (&h4.x)[u];
                    unsigned long long hh;
                    asm("mov.b64 %0, {%1, %1};" : "=l"(hh) : "f"(hv));
                    const unsigned long long w01 =
                        *(const unsigned long long*)(wcol + (kb + u) * 32);
                    const unsigned long long w23 =
                        *(const unsigned long long*)(wcol + (kb + u) * 32 + 2);
                    asm("fma.rn.f32x2 %0, %1, %2, %0;" : "+l"(a01) : "l"(hh), "l"(w01));
                    asm("fma.rn.f32x2 %0, %1, %2, %0;" : "+l"(a23) : "l"(hh), "l"(w23));
                }
            }
        }
        float acc0, acc1, acc2, acc3;
        asm("mov.b64 {%0, %1}, %2;" : "=f"(acc0), "=f"(acc1) : "l"(a01));
        asm("mov.b64 {%0, %1}, %2;" : "=f"(acc2), "=f"(acc3) : "l"(a23));

        // ---- Epilogue: h = relu(acc + pre), in place ----
        float* dst = net + ((size_t)(b0 + tm) * T + t) * H + j0 + tn * 4;
        float4 pre = __ldcg((const float4*)dst);
        float4 r;
        r.x = fmaxf(acc0 + pre.x, 0.f);
        r.y = fmaxf(acc1 + pre.y, 0.f);
        r.z = fmaxf(acc2 + pre.z, 0.f);
        r.w = fmaxf(acc3 + pre.w, 0.f);
        *(float4*)dst = r;
    }
}

// ---------------------------------------------------------------------------
// Readout: ro[b,t,o] = net[b,t,:].W_fc[o,:] + b_fc[o]; out/hidden from t=T-1
// ---------------------------------------------------------------------------
__global__ __launch_bounds__(256) void readout_kernel(
    const float* __restrict__ net, const float* __restrict__ W_fc,
    const float* __restrict__ b_fc, float* __restrict__ ro,
    float* __restrict__ out, float* __restrict__ hidden)
{
    __shared__ float4 w0s[H / 4];
    __shared__ float4 w1s[H / 4];
    const int tid = threadIdx.x;
    if (tid < H / 4)            w0s[tid]         = ((const float4*)W_fc)[tid];
    else if (tid < 2 * (H / 4)) w1s[tid - H / 4] = ((const float4*)(W_fc + H))[tid - H / 4];
    __syncthreads();

    const int warp = tid >> 5, lane = tid & 31;
    const int bt = blockIdx.x * 8 + warp;
    const int b = bt / T, t = bt % T;

    const float4* row = (const float4*)(net + (size_t)bt * H);
    float a0 = 0.f, a1 = 0.f;
    float4 vals[4];
    #pragma unroll
    for (int i = 0; i < 4; i++) {
        float4 v  = row[lane + 32 * i];
        float4 w0 = w0s[lane + 32 * i];
        float4 w1 = w1s[lane + 32 * i];
        vals[i] = v;
        a0 += v.x * w0.x + v.y * w0.y + v.z * w0.z + v.w * w0.w;
        a1 += v.x * w1.x + v.y * w1.y + v.z * w1.z + v.w * w1.w;
    }
    #pragma unroll
    for (int s = 16; s > 0; s >>= 1) {
        a0 += __shfl_xor_sync(0xFFFFFFFFu, a0, s);
        a1 += __shfl_xor_sync(0xFFFFFFFFu, a1, s);
    }
    if (lane == 0) {
        ro[(size_t)bt * 2 + 0] = a0 + b_fc[0];
        ro[(size_t)bt * 2 + 1] = a1 + b_fc[1];
    }
    if (t == T - 1) {
        if (lane == 0) {
            out[b * 2 + 0] = a0 + b_fc[0];
            out[b * 2 + 1] = a1 + b_fc[1];
        }
        float4* hid = (float4*)(hidden + (size_t)b * H);
        #pragma unroll
        for (int i = 0; i < 4; i++) hid[lane + 32 * i] = vals[i];
    }
}

extern "C" void kernel_launch(void* const* d_in, const int* in_sizes, int n_in,
                              void* d_out, int out_size)
{
    const float* input = (const float*)d_in[0];
    const float* sigma = (const float*)d_in[1];
    const float* noise = (const float*)d_in[2];
    const float* W_in  = (const float*)d_in[3];
    const float* b_in  = (const float*)d_in[4];
    const float* W_hh  = (const float*)d_in[5];
    const float* b_hh  = (const float*)d_in[6];
    const float* W_fc  = (const float*)d_in[7];
    const float* b_fc  = (const float*)d_in[8];

    float* out    = (float*)d_out;
    float* hidden = out + HID_OFF;
    float* net    = out + NET_OFF;
    float* ro     = out + RO_OFF;

    // Reset barrier counters (graph-capturable async memset)
    void* ctr_ptr = nullptr;
    cudaGetSymbolAddress(&ctr_ptr, g_ctr);
    cudaMemsetAsync(ctr_ptr, 0, T * sizeof(int), 0);

    // Fold input projection + biases + noise into net
    {
        dim3 g(T, B);
        pre_kernel<<<g, 128>>>(input, sigma, noise, W_in, b_in, b_hh, net);
    }

    // Persistent recurrence (one kernel, 511 internal global barriers)
    cudaFuncSetAttribute(rnn_persistent_kernel,
                         cudaFuncAttributeMaxDynamicSharedMemorySize, SMEM_BYTES);
    rnn_persistent_kernel<<<NCTA, NTHREADS, SMEM_BYTES>>>(W_hh, net);

    readout_kernel<<<(B * T) / 8, 256>>>(net, W_fc, b_fc, ro, out, hidden);
}

// round 6
// speedup vs baseline: 1.6721x; 1.6721x over previous
#include <cuda_runtime.h>

// Problem constants
#define B 256
#define T 512
#define H 512
#define O 2

// d_out layout (floats): out, hidden, net_units, read_out_units
#define HID_OFF (B * O)
#define NET_OFF (HID_OFF + B * H)
#define RO_OFF  (NET_OFF + B * T * H)

#define NCTA     128        // 16 j-tiles x 8 b-tiles
#define NTHREADS 512
#define GRP      16         // CTAs per b-group (all j-tiles of one b-tile)
#define HROW     516        // Hs row stride (4-bank skew per row -> conflict-free)

// smem: Ws[512][32] | Hs[32][HROW] | Rs[256] float4
#define WS_FLOATS (512 * 32)
#define HS_FLOATS (32 * HROW)
#define RS_FLOATS (256 * 4)
#define SMEM_BYTES ((WS_FLOATS + HS_FLOATS + RS_FLOATS) * 4)

// Per-(b-group, step) barrier counters. Row stride 512 ints -> groups on
// different cache lines. Reset by cudaMemsetAsync each launch.
__device__ int g_bar[8 * 512];

// ---------------------------------------------------------------------------
// Pre-pass: net[b,t,j] = input.W_in + b_in + b_hh + sigma*noise
// Thread owns one j-float4 for 8 consecutive t: coefs loaded once.
// ---------------------------------------------------------------------------
__global__ __launch_bounds__(128) void pre_kernel(
    const float* __restrict__ input, const float* __restrict__ sigma,
    const float* __restrict__ noise, const float* __restrict__ W_in,
    const float* __restrict__ b_in,  const float* __restrict__ b_hh,
    float* __restrict__ net)
{
    const int b  = blockIdx.x;
    const int t0 = blockIdx.y * 8;
    const int j  = threadIdx.x * 4;

    // coefs (register-cached across the 8 timesteps)
    float4 wi0 = *(const float4*)(W_in + j * 2);       // rows j, j+1
    float4 wi1 = *(const float4*)(W_in + j * 2 + 4);   // rows j+2, j+3
    float4 bi  = *(const float4*)(b_in + j);
    float4 bh  = *(const float4*)(b_hh + j);
    float4 c;
    c.x = bi.x + bh.x; c.y = bi.y + bh.y; c.z = bi.z + bh.z; c.w = bi.w + bh.w;
    const float sn = sigma[0];

    #pragma unroll
    for (int tt = 0; tt < 8; tt++) {
        const int t = t0 + tt;
        const size_t bt = (size_t)b * T + t;
        const float in0 = input[bt * 2 + 0];
        const float in1 = input[bt * 2 + 1];
        float4 nz = *(const float4*)(noise + bt * H + j);
        float4 r;
        r.x = in0 * wi0.x + in1 * wi0.y + c.x + sn * nz.x;
        r.y = in0 * wi0.z + in1 * wi0.w + c.y + sn * nz.y;
        r.z = in0 * wi1.x + in1 * wi1.y + c.z + sn * nz.z;
        r.w = in0 * wi1.z + in1 * wi1.w + c.w + sn * nz.w;
        *(float4*)(net + bt * H + j) = r;
    }
}

// ---------------------------------------------------------------------------
// Persistent recurrence. CTA: jt = bid & 15, bt-group = bid >> 4.
// 512 threads: kh = tid>>8 (k-half), r = tid&255, tm = r>>3, tn = r&7.
// Thread accumulates 4 outputs (row b0+tm, cols j0+4tn..+3) over 256 k.
// ---------------------------------------------------------------------------
__global__ __launch_bounds__(NTHREADS, 1) void rnn_persistent_kernel(
    const float* __restrict__ W_hh,   // [H,H]
    float*       __restrict__ net)    // [B,T,H]
{
    extern __shared__ float smem[];
    float*  Ws = smem;                        // Ws[k*32 + j]
    float*  Hs = smem + WS_FLOATS;            // Hs[m*HROW + k]
    float4* Rs = (float4*)(smem + WS_FLOATS + HS_FLOATS);

    const int tid = threadIdx.x;
    const int jt  = blockIdx.x & 15;
    const int bg  = blockIdx.x >> 4;
    const int j0  = jt * 32;
    const int b0  = bg * 32;

    const int kh = tid >> 8;       // k-half
    const int r  = tid & 255;
    const int tm = r >> 3;         // output row 0..31
    const int tn = r & 7;          // -> 4 cols

    int* bar = g_bar + bg * 512;

    // ---- Load W tile once: Ws[k][j] = W_hh[j0+j][k] ----
    {
        const int wj = tid & 31;
        const int wk = (tid >> 5) * 32;
        const float* src = W_hh + (size_t)(j0 + wj) * H + wk;
        #pragma unroll
        for (int c = 0; c < 32; c += 4) {
            float4 v = *(const float4*)(src + c);
            Ws[(wk + c + 0) * 32 + wj] = v.x;
            Ws[(wk + c + 1) * 32 + wj] = v.y;
            Ws[(wk + c + 2) * 32 + wj] = v.z;
            Ws[(wk + c + 3) * 32 + wj] = v.w;
        }
    }

    // ---- t = 0: h = relu(pre) ----
    if (tid < 256) {
        float* dst = net + ((size_t)(b0 + tm) * T + 0) * H + j0 + tn * 4;
        float4 p = __ldcg((const float4*)dst);
        p.x = fmaxf(p.x, 0.f); p.y = fmaxf(p.y, 0.f);
        p.z = fmaxf(p.z, 0.f); p.w = fmaxf(p.w, 0.f);
        *(float4*)dst = p;
    }

    // h loader mapping: 2 rows per warp, coalesced 64-float spans
    const int hrow = tid >> 4;        // 0..31
    const int hq4  = (tid & 15) * 4;  // float4 col within 64-float span

    const float* hrowS = Hs + tm * HROW;
    const float* wcol  = Ws + tn * 4;

    for (int t = 1; t < T; t++) {
        __syncthreads();                               // [A] step t-1 stores done
        if (tid == 0) {
            __threadfence();
            atomicAdd(&bar[t - 1], 1);
            while (*(volatile int*)&bar[t - 1] < GRP) __nanosleep(64);
            __threadfence();
        }
        __syncthreads();                               // [B]

        // ---- Load h(t-1) tile: 8 LDG.128, chunks: wave0 = k{0..127,256..383},
        //      wave1 = k{128..255,384..511} ----
        const float* src = net + ((size_t)(b0 + hrow) * T + (size_t)(t - 1)) * H + hq4;
        float4 v0 = __ldcg((const float4*)(src +   0));
        float4 v1 = __ldcg((const float4*)(src +  64));
        float4 v2 = __ldcg((const float4*)(src + 256));
        float4 v3 = __ldcg((const float4*)(src + 320));
        float4 v4 = __ldcg((const float4*)(src + 128));
        float4 v5 = __ldcg((const float4*)(src + 192));
        float4 v6 = __ldcg((const float4*)(src + 384));
        float4 v7 = __ldcg((const float4*)(src + 448));

        float* drow = Hs + hrow * HROW + hq4;
        *(float4*)(drow +   0) = v0;
        *(float4*)(drow +  64) = v1;
        *(float4*)(drow + 256) = v2;
        *(float4*)(drow + 320) = v3;
        __syncthreads();                               // [C] wave0 staged

        *(float4*)(drow + 128) = v4;
        *(float4*)(drow + 192) = v5;
        *(float4*)(drow + 384) = v6;
        *(float4*)(drow + 448) = v7;

        // ---- Compute: FFMA2, 4 outputs/thread over this thread's k-half ----
        unsigned long long a01 = 0ULL, a23 = 0ULL;
        {
            const int kb0 = kh * 256;                  // wave0 chunk
            #pragma unroll 2
            for (int kb = kb0; kb < kb0 + 128; kb += 4) {
                float4 h4 = *(const float4*)(hrowS + kb);
                #pragma unroll
                for (int u = 0; u < 4; u++) {
                    const float hv = (&h4.x)[u];
                    unsigned long long hh;
                    asm("mov.b64 %0, {%1, %1};" : "=l"(hh) : "f"(hv));
                    const unsigned long long w01 =
                        *(const unsigned long long*)(wcol + (kb + u) * 32);
                    const unsigned long long w23 =
                        *(const unsigned long long*)(wcol + (kb + u) * 32 + 2);
                    asm("fma.rn.f32x2 %0, %1, %2, %0;" : "+l"(a01) : "l"(hh), "l"(w01));
                    asm("fma.rn.f32x2 %0, %1, %2, %0;" : "+l"(a23) : "l"(hh), "l"(w23));
                }
            }
        }
        __syncthreads();                               // [D] wave1 staged
        {
            const int kb0 = kh * 256 + 128;            // wave1 chunk
            #pragma unroll 2
            for (int kb = kb0; kb < kb0 + 128; kb += 4) {
                float4 h4 = *(const float4*)(hrowS + kb);
                #pragma unroll
                for (int u = 0; u < 4; u++) {
                    const float hv = (&h4.x)[u];
                    unsigned long long hh;
                    asm("mov.b64 %0, {%1, %1};" : "=l"(hh) : "f"(hv));
                    const unsigned long long w01 =
                        *(const unsigned long long*)(wcol + (kb + u) * 32);
                    const unsigned long long w23 =
                        *(const unsigned long long*)(wcol + (kb + u) * 32 + 2);
                    asm("fma.rn.f32x2 %0, %1, %2, %0;" : "+l"(a01) : "l"(hh), "l"(w01));
                    asm("fma.rn.f32x2 %0, %1, %2, %0;" : "+l"(a23) : "l"(hh), "l"(w23));
                }
            }
        }

        float acc0, acc1, acc2, acc3;
        asm("mov.b64 {%0, %1}, %2;" : "=f"(acc0), "=f"(acc1) : "l"(a01));
        asm("mov.b64 {%0, %1}, %2;" : "=f"(acc2), "=f"(acc3) : "l"(a23));

        __syncthreads();                               // [E] compute done
        if (kh == 1) {
            float4 p; p.x = acc0; p.y = acc1; p.z = acc2; p.w = acc3;
            Rs[r] = p;
        }
        __syncthreads();                               // [F] partials staged
        if (kh == 0) {
            float4 p = Rs[r];
            float* dst = net + ((size_t)(b0 + tm) * T + t) * H + j0 + tn * 4;
            float4 pre = __ldcg((const float4*)dst);
            float4 o;
            o.x = fmaxf(acc0 + p.x + pre.x, 0.f);
            o.y = fmaxf(acc1 + p.y + pre.y, 0.f);
            o.z = fmaxf(acc2 + p.z + pre.z, 0.f);
            o.w = fmaxf(acc3 + p.w + pre.w, 0.f);
            *(float4*)dst = o;
        }
    }
}

// ---------------------------------------------------------------------------
// Readout: ro[b,t,o] = net[b,t,:].W_fc[o,:] + b_fc[o]; out/hidden from t=T-1
// ---------------------------------------------------------------------------
__global__ __launch_bounds__(256) void readout_kernel(
    const float* __restrict__ net, const float* __restrict__ W_fc,
    const float* __restrict__ b_fc, float* __restrict__ ro,
    float* __restrict__ out, float* __restrict__ hidden)
{
    __shared__ float4 w0s[H / 4];
    __shared__ float4 w1s[H / 4];
    const int tid = threadIdx.x;
    if (tid < H / 4)            w0s[tid]         = ((const float4*)W_fc)[tid];
    else if (tid < 2 * (H / 4)) w1s[tid - H / 4] = ((const float4*)(W_fc + H))[tid - H / 4];
    __syncthreads();

    const int warp = tid >> 5, lane = tid & 31;
    const int bt = blockIdx.x * 8 + warp;
    const int b = bt / T, t = bt % T;

    const float4* row = (const float4*)(net + (size_t)bt * H);
    float a0 = 0.f, a1 = 0.f;
    float4 vals[4];
    #pragma unroll
    for (int i = 0; i < 4; i++) {
        float4 v  = row[lane + 32 * i];
        float4 w0 = w0s[lane + 32 * i];
        float4 w1 = w1s[lane + 32 * i];
        vals[i] = v;
        a0 += v.x * w0.x + v.y * w0.y + v.z * w0.z + v.w * w0.w;
        a1 += v.x * w1.x + v.y * w1.y + v.z * w1.z + v.w * w1.w;
    }
    #pragma unroll
    for (int s = 16; s > 0; s >>= 1) {
        a0 += __shfl_xor_sync(0xFFFFFFFFu, a0, s);
        a1 += __shfl_xor_sync(0xFFFFFFFFu, a1, s);
    }
    if (lane == 0) {
        ro[(size_t)bt * 2 + 0] = a0 + b_fc[0];
        ro[(size_t)bt * 2 + 1] = a1 + b_fc[1];
    }
    if (t == T - 1) {
        if (lane == 0) {
            out[b * 2 + 0] = a0 + b_fc[0];
            out[b * 2 + 1] = a1 + b_fc[1];
        }
        float4* hid = (float4*)(hidden + (size_t)b * H);
        #pragma unroll
        for (int i = 0; i < 4; i++) hid[lane + 32 * i] = vals[i];
    }
}

extern "C" void kernel_launch(void* const* d_in, const int* in_sizes, int n_in,
                              void* d_out, int out_size)
{
    const float* input = (const float*)d_in[0];
    const float* sigma = (const float*)d_in[1];
    const float* noise = (const float*)d_in[2];
    const float* W_in  = (const float*)d_in[3];
    const float* b_in  = (const float*)d_in[4];
    const float* W_hh  = (const float*)d_in[5];
    const float* b_hh  = (const float*)d_in[6];
    const float* W_fc  = (const float*)d_in[7];
    const float* b_fc  = (const float*)d_in[8];

    float* out    = (float*)d_out;
    float* hidden = out + HID_OFF;
    float* net    = out + NET_OFF;
    float* ro     = out + RO_OFF;

    // Reset barrier counters (graph-capturable)
    void* bar_ptr = nullptr;
    cudaGetSymbolAddress(&bar_ptr, g_bar);
    cudaMemsetAsync(bar_ptr, 0, 8 * 512 * sizeof(int), 0);

    // Pre-pass: fold input projection + biases + noise into net
    {
        dim3 g(B, T / 8);
        pre_kernel<<<g, 128>>>(input, sigma, noise, W_in, b_in, b_hh, net);
    }

    // Persistent recurrence
    cudaFuncSetAttribute(rnn_persistent_kernel,
                         cudaFuncAttributeMaxDynamicSharedMemorySize, SMEM_BYTES);
    rnn_persistent_kernel<<<NCTA, NTHREADS, SMEM_BYTES>>>(W_hh, net);

    readout_kernel<<<(B * T) / 8, 256>>>(net, W_fc, b_fc, ro, out, hidden);
}

// round 9
// speedup vs baseline: 1.8266x; 1.0924x over previous
#include <cuda_runtime.h>

// Problem constants
#define B 256
#define T 512
#define H 512
#define O 2

// d_out layout (floats): out, hidden, net_units, read_out_units
#define HID_OFF (B * O)
#define NET_OFF (HID_OFF + B * H)
#define RO_OFF  (NET_OFF + B * T * H)

#define NCTA     128        // 16 j-tiles x 8 b-groups
#define NTHREADS 512
#define GRP      16         // CTAs per b-group
#define HROW     516        // Hs row stride in floats (bank skew)

// smem (floats): Wp[256 kp][32 colpairs] as float2 = 16384 floats,
//                Hs[32][HROW], Rs[256] float4
#define WP_FLOATS (256 * 32 * 2)
#define HS_FLOATS (32 * HROW)
#define RS_FLOATS (256 * 4)
#define SMEM_BYTES ((WP_FLOATS + HS_FLOATS + RS_FLOATS) * 4)

// Per-(b-group, step) barrier counters; reset by cudaMemsetAsync each launch.
__device__ unsigned g_bar[8 * 512];

// ---------------------------------------------------------------------------
// Pre-pass: net[b,t,j] = input.W_in + b_in + b_hh + sigma*noise
// ---------------------------------------------------------------------------
__global__ __launch_bounds__(128) void pre_kernel(
    const float* __restrict__ input, const float* __restrict__ sigma,
    const float* __restrict__ noise, const float* __restrict__ W_in,
    const float* __restrict__ b_in,  const float* __restrict__ b_hh,
    float* __restrict__ net)
{
    const int b  = blockIdx.x;
    const int t0 = blockIdx.y * 8;
    const int j  = threadIdx.x * 4;

    float4 wi0 = *(const float4*)(W_in + j * 2);
    float4 wi1 = *(const float4*)(W_in + j * 2 + 4);
    float4 bi  = *(const float4*)(b_in + j);
    float4 bh  = *(const float4*)(b_hh + j);
    float4 c;
    c.x = bi.x + bh.x; c.y = bi.y + bh.y; c.z = bi.z + bh.z; c.w = bi.w + bh.w;
    const float sn = sigma[0];

    #pragma unroll
    for (int tt = 0; tt < 8; tt++) {
        const int t = t0 + tt;
        const size_t bt = (size_t)b * T + t;
        const float in0 = input[bt * 2 + 0];
        const float in1 = input[bt * 2 + 1];
        float4 nz = *(const float4*)(noise + bt * H + j);
        float4 r;
        r.x = in0 * wi0.x + in1 * wi0.y + c.x + sn * nz.x;
        r.y = in0 * wi0.z + in1 * wi0.w + c.y + sn * nz.y;
        r.z = in0 * wi1.x + in1 * wi1.y + c.z + sn * nz.z;
        r.w = in0 * wi1.z + in1 * wi1.w + c.w + sn * nz.w;
        *(float4*)(net + bt * H + j) = r;
    }
}

// ---------------------------------------------------------------------------
// Persistent recurrence. CTA: jt = bid & 15, bg = bid >> 4.
// 512 threads: kh = tid>>8 (k-half), r = tid&255, tm = r>>3, tn = r&7.
// Thread: 4 outputs (row b0+tm, cols j0+4tn..+3) over 256 k (128 k-pairs).
//
// Wp layout (per kp row of 32 ull colpairs): position of col c =
//   ((c&2)<<3) + ((c>>2)<<1) + (c&1)
// so thread tn's two 16B loads (cols 4tn..4tn+1 and 4tn+2..4tn+3) sit at
// byte offsets tn*16 and 128 + tn*16 -> conflict-free LDS.128 across the warp.
// ---------------------------------------------------------------------------
__global__ __launch_bounds__(NTHREADS, 1) void rnn_persistent_kernel(
    const float* __restrict__ W_hh,   // [H,H]
    float*       __restrict__ net)    // [B,T,H]
{
    extern __shared__ float smem[];
    float*  Wp = smem;                              // k-pair W tile
    float*  Hs = smem + WP_FLOATS;                  // Hs[m*HROW + k]
    float4* Rs = (float4*)(smem + WP_FLOATS + HS_FLOATS);

    const int tid = threadIdx.x;
    const int jt  = blockIdx.x & 15;
    const int bg  = blockIdx.x >> 4;
    const int j0  = jt * 32;
    const int b0  = bg * 32;

    const int kh = tid >> 8;
    const int r  = tid & 255;
    const int tm = r >> 3;
    const int tn = r & 7;

    unsigned* barp = g_bar + bg * 512;

    // ---- Load W tile once into k-pair permuted layout ----
    {
        const int wj  = tid & 31;                  // col within tile (W row j0+wj)
        const int wk  = (tid >> 5) * 32;           // 32 k per thread
        const int pos = ((wj & 2) << 3) + ((wj >> 2) << 1) + (wj & 1);
        const float* src = W_hh + (size_t)(j0 + wj) * H + wk;
        float2* WpF2 = (float2*)Wp;
        #pragma unroll
        for (int c = 0; c < 32; c += 4) {
            float4 v = *(const float4*)(src + c);
            const int kp = (wk + c) >> 1;
            WpF2[(kp + 0) * 32 + pos] = make_float2(v.x, v.y);
            WpF2[(kp + 1) * 32 + pos] = make_float2(v.z, v.w);
        }
    }

    // ---- t = 0: h = relu(pre) ----
    if (kh == 0) {
        float* dst = net + ((size_t)(b0 + tm) * T + 0) * H + j0 + tn * 4;
        float4 p = __ldcg((const float4*)dst);
        p.x = fmaxf(p.x, 0.f); p.y = fmaxf(p.y, 0.f);
        p.z = fmaxf(p.z, 0.f); p.w = fmaxf(p.w, 0.f);
        *(float4*)dst = p;
    }

    // h loader mapping: row = tid>>4 (0..31), 16 threads span 64 floats
    const int hrow = tid >> 4;
    const int hq4  = (tid & 15) * 4;

    const float* hrowS = Hs + tm * HROW;
    const unsigned long long* wq = ((const unsigned long long*)Wp) + tn * 2;
    float* dst0 = net + (size_t)(b0 + tm) * T * H + j0 + tn * 4;   // + t*H

    for (int t = 1; t < T; t++) {
        __syncthreads();                           // [A] epilogue stores issued
        if (tid == 0) {
            unsigned* p = barp + (t - 1);
            asm volatile("red.release.gpu.global.add.u32 [%0], 1;"
                         :: "l"(p) : "memory");
            unsigned v;
            do {
                asm volatile("ld.acquire.gpu.global.u32 %0, [%1];"
                             : "=r"(v) : "l"(p) : "memory");
            } while (v < GRP);
        }
        __syncthreads();                           // [B] h(t-1) globally visible

        // ---- Issue all loads up front: 8 h LDG.128 + pre prefetch ----
        const float* src = net + ((size_t)(b0 + hrow) * T + (size_t)(t - 1)) * H + hq4;
        float4 v0 = __ldcg((const float4*)(src +   0));
        float4 v1 = __ldcg((const float4*)(src +  64));
        float4 v2 = __ldcg((const float4*)(src + 128));
        float4 v3 = __ldcg((const float4*)(src + 192));
        float4 v4 = __ldcg((const float4*)(src + 256));
        float4 v5 = __ldcg((const float4*)(src + 320));
        float4 v6 = __ldcg((const float4*)(src + 384));
        float4 v7 = __ldcg((const float4*)(src + 448));
        float4 prev;
        if (kh == 0) prev = __ldcg((const float4*)(dst0 + (size_t)t * H));

        float* drow = Hs + hrow * HROW + hq4;
        *(float4*)(drow +   0) = v0;
        *(float4*)(drow +  64) = v1;
        *(float4*)(drow + 128) = v2;
        *(float4*)(drow + 192) = v3;
        *(float4*)(drow + 256) = v4;
        *(float4*)(drow + 320) = v5;
        *(float4*)(drow + 384) = v6;
        *(float4*)(drow + 448) = v7;
        __syncthreads();                           // [C] h tile staged

        // ---- Compute: 128 k-pairs, 4 cols via paired-k FFMA2 ----
        unsigned long long a0 = 0ULL, a1 = 0ULL, a2 = 0ULL, a3 = 0ULL;
        {
            const int kp0 = kh * 128;
            #pragma unroll 4
            for (int kp = kp0; kp < kp0 + 128; kp++) {
                const unsigned long long hh =
                    *(const unsigned long long*)(hrowS + 2 * kp);
                const unsigned long long* wrow = wq + kp * 32;
                unsigned long long wA0 = wrow[0];
                unsigned long long wA1 = wrow[1];
                unsigned long long wB0 = wrow[16];
                unsigned long long wB1 = wrow[17];
                asm("fma.rn.f32x2 %0, %1, %2, %0;" : "+l"(a0) : "l"(hh), "l"(wA0));
                asm("fma.rn.f32x2 %0, %1, %2, %0;" : "+l"(a1) : "l"(hh), "l"(wA1));
                asm("fma.rn.f32x2 %0, %1, %2, %0;" : "+l"(a2) : "l"(hh), "l"(wB0));
                asm("fma.rn.f32x2 %0, %1, %2, %0;" : "+l"(a3) : "l"(hh), "l"(wB1));
            }
        }
        // combine the two k-halves inside each f32x2
        float acc0, acc1, acc2, acc3, lo, hi;
        asm("mov.b64 {%0, %1}, %2;" : "=f"(lo), "=f"(hi) : "l"(a0)); acc0 = lo + hi;
        asm("mov.b64 {%0, %1}, %2;" : "=f"(lo), "=f"(hi) : "l"(a1)); acc1 = lo + hi;
        asm("mov.b64 {%0, %1}, %2;" : "=f"(lo), "=f"(hi) : "l"(a2)); acc2 = lo + hi;
        asm("mov.b64 {%0, %1}, %2;" : "=f"(lo), "=f"(hi) : "l"(a3)); acc3 = lo + hi;

        if (kh == 1) {
            float4 p; p.x = acc0; p.y = acc1; p.z = acc2; p.w = acc3;
            Rs[r] = p;
        }
        __syncthreads();                           // [F] partials staged
        if (kh == 0) {
            float4 p = Rs[r];
            float4 o;
            o.x = fmaxf(acc0 + p.x + prev.x, 0.f);
            o.y = fmaxf(acc1 + p.y + prev.y, 0.f);
            o.z = fmaxf(acc2 + p.z + prev.z, 0.f);
            o.w = fmaxf(acc3 + p.w + prev.w, 0.f);
            *(float4*)(dst0 + (size_t)t * H) = o;
        }
    }
}

// ---------------------------------------------------------------------------
// Readout: ro[b,t,o] = net[b,t,:].W_fc[o,:] + b_fc[o]; out/hidden from t=T-1
// ---------------------------------------------------------------------------
__global__ __launch_bounds__(256) void readout_kernel(
    const float* __restrict__ net, const float* __restrict__ W_fc,
    const float* __restrict__ b_fc, float* __restrict__ ro,
    float* __restrict__ out, float* __restrict__ hidden)
{
    __shared__ float4 w0s[H / 4];
    __shared__ float4 w1s[H / 4];
    const int tid = threadIdx.x;
    if (tid < H / 4)            w0s[tid]         = ((const float4*)W_fc)[tid];
    else if (tid < 2 * (H / 4)) w1s[tid - H / 4] = ((const float4*)(W_fc + H))[tid - H / 4];
    __syncthreads();

    const int warp = tid >> 5, lane = tid & 31;
    const int bt = blockIdx.x * 8 + warp;
    const int b = bt / T, t = bt % T;

    const float4* row = (const float4*)(net + (size_t)bt * H);
    float a0 = 0.f, a1 = 0.f;
    float4 vals[4];
    #pragma unroll
    for (int i = 0; i < 4; i++) {
        float4 v  = row[lane + 32 * i];
        float4 w0 = w0s[lane + 32 * i];
        float4 w1 = w1s[lane + 32 * i];
        vals[i] = v;
        a0 += v.x * w0.x + v.y * w0.y + v.z * w0.z + v.w * w0.w;
        a1 += v.x * w1.x + v.y * w1.y + v.z * w1.z + v.w * w1.w;
    }
    #pragma unroll
    for (int s = 16; s > 0; s >>= 1) {
        a0 += __shfl_xor_sync(0xFFFFFFFFu, a0, s);
        a1 += __shfl_xor_sync(0xFFFFFFFFu, a1, s);
    }
    if (lane == 0) {
        ro[(size_t)bt * 2 + 0] = a0 + b_fc[0];
        ro[(size_t)bt * 2 + 1] = a1 + b_fc[1];
    }
    if (t == T - 1) {
        if (lane == 0) {
            out[b * 2 + 0] = a0 + b_fc[0];
            out[b * 2 + 1] = a1 + b_fc[1];
        }
        float4* hid = (float4*)(hidden + (size_t)b * H);
        #pragma unroll
        for (int i = 0; i < 4; i++) hid[lane + 32 * i] = vals[i];
    }
}

extern "C" void kernel_launch(void* const* d_in, const int* in_sizes, int n_in,
                              void* d_out, int out_size)
{
    const float* input = (const float*)d_in[0];
    const float* sigma = (const float*)d_in[1];
    const float* noise = (const float*)d_in[2];
    const float* W_in  = (const float*)d_in[3];
    const float* b_in  = (const float*)d_in[4];
    const float* W_hh  = (const float*)d_in[5];
    const float* b_hh  = (const float*)d_in[6];
    const float* W_fc  = (const float*)d_in[7];
    const float* b_fc  = (const float*)d_in[8];

    float* out    = (float*)d_out;
    float* hidden = out + HID_OFF;
    float* net    = out + NET_OFF;
    float* ro     = out + RO_OFF;

    // Reset barrier counters (graph-capturable)
    void* bar_ptr = nullptr;
    cudaGetSymbolAddress(&bar_ptr, g_bar);
    cudaMemsetAsync(bar_ptr, 0, 8 * 512 * sizeof(unsigned), 0);

    // Pre-pass
    {
        dim3 g(B, T / 8);
        pre_kernel<<<g, 128>>>(input, sigma, noise, W_in, b_in, b_hh, net);
    }

    // Persistent recurrence
    cudaFuncSetAttribute(rnn_persistent_kernel,
                         cudaFuncAttributeMaxDynamicSharedMemorySize, SMEM_BYTES);
    rnn_persistent_kernel<<<NCTA, NTHREADS, SMEM_BYTES>>>(W_hh, net);

    readout_kernel<<<(B * T) / 8, 256>>>(net, W_fc, b_fc, ro, out, hidden);
}